// round 15
// baseline (speedup 1.0000x reference)
#include <cuda_runtime.h>
#include <cuda_fp16.h>
#include <math.h>
#include <stdint.h>

// ---------------- problem constants ----------------
#define BB    4
#define TT    4096
#define DD    2048
#define MM    64
#define DZ    512
#define HH    16
#define DH    128
#define DFF   8192
#define BT    (BB*TT)     // 16384
#define BM_   (BB*MM)     // 256
#define KVS   (2*DD)      // fused KV row stride

// ---------------- device scratch ----------------
__device__ __half g_hn [BT * DD];
__device__ __half g_z  [BM_ * DZ];
__device__ __half g_WqT [DD * DD];        // [N,K] K-major
__device__ __half g_WkvT[KVS * DZ];
__device__ __half g_W1T [DFF * DD];
__device__ __half g_W2T [DD * DFF];
__device__ float  g_bkv [KVS];
__device__ __half g_KV [BM_ * KVS];       // K cols 0..D-1, V cols D..2D-1
__device__ __half g_ctx[BT * DD];
__device__ __half g_G  [BT * DFF];

// ---------------- side streams + events (created at load, outside capture) ----
struct SideStream {
    cudaStream_t s1, s2;
    cudaEvent_t  evF, evQ, evKV, ev1, ev2;
    SideStream() {
        cudaStreamCreateWithFlags(&s1, cudaStreamNonBlocking);
        cudaStreamCreateWithFlags(&s2, cudaStreamNonBlocking);
        cudaEventCreateWithFlags(&evF,  cudaEventDisableTiming);
        cudaEventCreateWithFlags(&evQ,  cudaEventDisableTiming);
        cudaEventCreateWithFlags(&evKV, cudaEventDisableTiming);
        cudaEventCreateWithFlags(&ev1,  cudaEventDisableTiming);
        cudaEventCreateWithFlags(&ev2,  cudaEventDisableTiming);
    }
};
static SideStream g_ss;

// ---------------- helpers ----------------
__device__ __forceinline__ float gelu_fast(float x) {
    float u = 0.7978845608028654f * fmaf(0.044715f * x, x * x, x);
    float t;
    asm("tanh.approx.f32 %0, %1;" : "=f"(t) : "f"(u));
    return 0.5f * x * (1.f + t);
}
__device__ __forceinline__ void cp_async16(uint32_t s, const void* g) {
    asm volatile("cp.async.cg.shared.global [%0], [%1], 16;" :: "r"(s), "l"(g));
}
__device__ __forceinline__ void cp_commit() {
    asm volatile("cp.async.commit_group;");
}
template<int N> __device__ __forceinline__ void cp_wait() {
    asm volatile("cp.async.wait_group %0;" :: "n"(N));
}
__device__ __forceinline__ void ldsm4(uint32_t& r0, uint32_t& r1, uint32_t& r2, uint32_t& r3,
                                      uint32_t addr) {
    asm volatile("ldmatrix.sync.aligned.m8n8.x4.shared.b16 {%0,%1,%2,%3}, [%4];"
        : "=r"(r0), "=r"(r1), "=r"(r2), "=r"(r3) : "r"(addr));
}
__device__ __forceinline__ void mma16816(float* c,
                                         uint32_t a0, uint32_t a1, uint32_t a2, uint32_t a3,
                                         uint32_t b0, uint32_t b1) {
    asm volatile(
        "mma.sync.aligned.m16n8k16.row.col.f32.f16.f16.f32 "
        "{%0,%1,%2,%3}, {%4,%5,%6,%7}, {%8,%9}, {%0,%1,%2,%3};"
        : "+f"(c[0]), "+f"(c[1]), "+f"(c[2]), "+f"(c[3])
        : "r"(a0), "r"(a1), "r"(a2), "r"(a3), "r"(b0), "r"(b1));
}

// ---------------- elementwise fp32 -> fp16 ----------------
__global__ void to_half_kernel(const float* __restrict__ in, __half* __restrict__ out, int n4) {
    int i = blockIdx.x * blockDim.x + threadIdx.x;
    if (i < n4) {
        float4 v = ((const float4*)in)[i];
        __half2 h0 = __floats2half2_rn(v.x, v.y);
        __half2 h1 = __floats2half2_rn(v.z, v.w);
        uint2 o; o.x = *(uint32_t*)&h0; o.y = *(uint32_t*)&h1;
        ((uint2*)out)[i] = o;
    }
}

// ---------------- bias concat ----------------
__global__ void bias_concat_kernel(const float* __restrict__ bk, const float* __restrict__ bv,
                                   float* __restrict__ bkv) {
    int i = blockIdx.x * blockDim.x + threadIdx.x;
    if (i < DD) { bkv[i] = bk[i]; bkv[DD + i] = bv[i]; }
}

// ---------------- weight transpose: W[K,N] fp32 -> Wt[N,K] fp16 ----------------
__global__ __launch_bounds__(256) void transpose_half(
    const float* __restrict__ W, __half* __restrict__ Wt, int K, int N)
{
    __shared__ float t[32][33];
    int n0 = blockIdx.x * 32, k0 = blockIdx.y * 32;
    int tx = threadIdx.x, ty = threadIdx.y;   // 32 x 8
    #pragma unroll
    for (int i = 0; i < 32; i += 8)
        t[ty + i][tx] = W[(size_t)(k0 + ty + i) * N + n0 + tx];
    __syncthreads();
    int tid = ty * 32 + tx;
    int kl = (tid & 15) * 2;
    #pragma unroll
    for (int i = 0; i < 2; i++) {
        int nl = (tid >> 4) + i * 16;
        __half2 hv = __floats2half2_rn(t[kl][nl], t[kl + 1][nl]);
        *(__half2*)&Wt[(size_t)(n0 + nl) * K + k0 + kl] = hv;
    }
}

// ---------------- LayerNorm: fp32 in, fp16 out ----------------
__global__ __launch_bounds__(256) void ln_kernel(
    const float* __restrict__ h, const float* __restrict__ g,
    const float* __restrict__ b, __half* __restrict__ out)
{
    int row = blockIdx.x;
    const float4* x4 = (const float4*)(h + (size_t)row * DD);
    int tx = threadIdx.x;
    float4 v0 = x4[tx], v1 = x4[tx + 256];
    float s  = v0.x + v0.y + v0.z + v0.w + v1.x + v1.y + v1.z + v1.w;
    float s2 = v0.x*v0.x + v0.y*v0.y + v0.z*v0.z + v0.w*v0.w
             + v1.x*v1.x + v1.y*v1.y + v1.z*v1.z + v1.w*v1.w;
    int lane = tx & 31, warp = tx >> 5;
    #pragma unroll
    for (int o = 16; o; o >>= 1) {
        s  += __shfl_xor_sync(0xffffffffu, s,  o);
        s2 += __shfl_xor_sync(0xffffffffu, s2, o);
    }
    __shared__ float sh[16];
    if (lane == 0) { sh[warp] = s; sh[warp + 8] = s2; }
    __syncthreads();
    float ts = 0.f, ts2 = 0.f;
    #pragma unroll
    for (int i = 0; i < 8; i++) { ts += sh[i]; ts2 += sh[i + 8]; }
    float mu  = ts * (1.f / DD);
    float var = ts2 * (1.f / DD) - mu * mu;
    float inv = rsqrtf(var + 1e-5f);

    const float4* g4 = (const float4*)g;
    const float4* b4 = (const float4*)b;
    uint2* o4 = (uint2*)(out + (size_t)row * DD);
    #pragma unroll
    for (int half_i = 0; half_i < 2; half_i++) {
        float4 v = half_i ? v1 : v0;
        int idx = tx + half_i * 256;
        float4 ga = g4[idx], bb = b4[idx];
        float y0 = (v.x - mu) * inv * ga.x + bb.x;
        float y1 = (v.y - mu) * inv * ga.y + bb.y;
        float y2 = (v.z - mu) * inv * ga.z + bb.z;
        float y3 = (v.w - mu) * inv * ga.w + bb.w;
        __half2 h0 = __floats2half2_rn(y0, y1);
        __half2 h1 = __floats2half2_rn(y2, y3);
        uint2 o; o.x = *(uint32_t*)&h0; o.y = *(uint32_t*)&h1;
        o4[idx] = o;
    }
}

// ---------------- fp16 GEMM (champion, for KV/FFN1/FFN2) ----------------
template<int EPI>
__global__ void __launch_bounds__(256, 2) gemm_fp16(
    const __half* __restrict__ A, const __half* __restrict__ Bt,
    const float* __restrict__ bias, void* __restrict__ Cv,
    int Mdim, int Ndim, int Kdim,
    const float* __restrict__ res, const float* __restrict__ alpha)
{
    constexpr int STAGE = 32768;
    extern __shared__ __align__(128) char smem[];
    uint32_t sb = (uint32_t)__cvta_generic_to_shared(smem);
    const int tid  = threadIdx.x;
    const int lane = tid & 31, warp = tid >> 5;
    const int wm = (warp & 3) * 32, wn = (warp >> 2) * 64;

    int gm = Mdim >> 7, gn = Ndim >> 7;
    int pid = blockIdx.x;
    const int GRP = 8;
    int width = GRP * gn;
    int grp = pid / width;
    int first = grp * GRP;
    int sz = min(gm - first, GRP);
    int mt = first + (pid % sz);
    int nt = (pid % width) / sz;
    const int bm = mt << 7, bn = nt << 7;

    float acc[2][8][4];
    #pragma unroll
    for (int i = 0; i < 2; i++)
        #pragma unroll
        for (int j = 0; j < 8; j++)
            #pragma unroll
            for (int k = 0; k < 4; k++) acc[i][j][k] = 0.f;

    const int KT = Kdim >> 6;

    const int lrow = tid >> 3, lch = tid & 7;
    auto loadTile = [&](int kt, int st) {
        uint32_t base = sb + st * STAGE;
        const __half* Ag = A  + (size_t)bm * Kdim + kt * 64 + lch * 8;
        const __half* Bg = Bt + (size_t)bn * Kdim + kt * 64 + lch * 8;
        #pragma unroll
        for (int i = 0; i < 4; i++) {
            int r = lrow + i * 32;
            uint32_t sw = (uint32_t)(lch ^ (r & 7)) << 4;
            cp_async16(base + r * 128 + sw,         Ag + (size_t)r * Kdim);
            cp_async16(base + 16384 + r * 128 + sw, Bg + (size_t)r * Kdim);
        }
        cp_commit();
    };

    loadTile(0, 0); loadTile(1, 1);

    const int ar0 = wm + (lane & 15);
    const int brr = wn + (lane & 7) + ((lane >> 4) << 3);
    const int a_l16 = (lane >> 4);
    const int b_l8  = (lane >> 3) & 1;

    int st = 0;
    for (int kt = 0; kt < KT; ++kt) {
        cp_wait<1>();
        __syncthreads();
        if (kt + 2 < KT) {
            int nst = st + 2; if (nst >= 3) nst -= 3;
            loadTile(kt + 2, nst);
        } else {
            cp_commit();
        }

        uint32_t Ab = sb + st * STAGE;
        uint32_t Bb = Ab + 16384;
        #pragma unroll
        for (int ks = 0; ks < 4; ++ks) {
            uint32_t a[2][4];
            int ach = ks * 2 + a_l16;
            #pragma unroll
            for (int mi = 0; mi < 2; mi++) {
                int r = ar0 + mi * 16;
                uint32_t addr = Ab + r * 128 + (((uint32_t)(ach ^ (r & 7))) << 4);
                ldsm4(a[mi][0], a[mi][1], a[mi][2], a[mi][3], addr);
            }
            int bch = ks * 2 + b_l8;
            #pragma unroll
            for (int ni = 0; ni < 4; ni++) {
                int r = brr + ni * 16;
                uint32_t addr = Bb + r * 128 + (((uint32_t)(bch ^ (r & 7))) << 4);
                uint32_t b0, b1, b2, b3;
                ldsm4(b0, b1, b2, b3, addr);
                #pragma unroll
                for (int mi = 0; mi < 2; mi++) {
                    mma16816(acc[mi][ni * 2    ], a[mi][0], a[mi][1], a[mi][2], a[mi][3], b0, b1);
                    mma16816(acc[mi][ni * 2 + 1], a[mi][0], a[mi][1], a[mi][2], a[mi][3], b2, b3);
                }
            }
        }
        if (++st == 3) st = 0;
    }

    float ta = 0.f;
    if (EPI == 2) ta = tanhf(*alpha);
    const int r0 = bm + wm + (lane >> 2);
    const int c0 = bn + wn + (lane & 3) * 2;
    #pragma unroll
    for (int mi = 0; mi < 2; mi++) {
        #pragma unroll
        for (int nj = 0; nj < 8; nj++) {
            int col = c0 + nj * 8;
            float2 bv = *(const float2*)&bias[col];
            #pragma unroll
            for (int hf = 0; hf < 2; hf++) {
                int row = r0 + mi * 16 + hf * 8;
                float v0 = acc[mi][nj][hf * 2    ] + bv.x;
                float v1 = acc[mi][nj][hf * 2 + 1] + bv.y;
                size_t off = (size_t)row * Ndim + col;
                if (EPI == 0) {
                    __half2 hv = __floats2half2_rn(v0, v1);
                    *(__half2*)((__half*)Cv + off) = hv;
                } else if (EPI == 1) {
                    __half2 hv = __floats2half2_rn(gelu_fast(v0), gelu_fast(v1));
                    *(__half2*)((__half*)Cv + off) = hv;
                } else {
                    float2 rr = *(const float2*)&res[off];
                    float2 o; o.x = rr.x + ta * v0; o.y = rr.y + ta * v1;
                    *(float2*)((float*)Cv + off) = o;
                }
            }
        }
    }
}

// ---------------- FUSED Q-projection + cross-attention (R14 champion) ----------------
__global__ void __launch_bounds__(256, 2) qproj_attn(
    const __half* __restrict__ A, const __half* __restrict__ Bt,
    const float* __restrict__ bias, const __half* __restrict__ kv,
    __half* __restrict__ ctx)
{
    constexpr int Mdim = BT, Ndim = DD, Kdim = DD;
    constexpr int STAGE = 32768;
    extern __shared__ __align__(128) char smem[];
    uint32_t sb = (uint32_t)__cvta_generic_to_shared(smem);
    const uint32_t QS = 0, KS = 32768, VT = 49152, PS = 65536;
    const int tid  = threadIdx.x;
    const int lane = tid & 31, warp = tid >> 5;
    const int wm = (warp & 3) * 32, wn = (warp >> 2) * 64;

    int gm = Mdim >> 7, gn = Ndim >> 7;
    int pid = blockIdx.x;
    const int GRP = 8;
    int width = GRP * gn;
    int grp = pid / width;
    int first = grp * GRP;
    int sz = min(gm - first, GRP);
    int mt = first + (pid % sz);
    int nt = (pid % width) / sz;
    const int bm = mt << 7, bn = nt << 7;
    const int b  = bm >> 12;
    const int t0 = bm & (TT - 1);
    const int hh = nt;

    float acc[2][8][4];
    #pragma unroll
    for (int i = 0; i < 2; i++)
        #pragma unroll
        for (int j = 0; j < 8; j++)
            #pragma unroll
            for (int k = 0; k < 4; k++) acc[i][j][k] = 0.f;

    const int KT = Kdim >> 6;

    const int lrow = tid >> 3, lch = tid & 7;
    auto loadTile = [&](int kt, int st) {
        uint32_t base = sb + st * STAGE;
        const __half* Ag = A  + (size_t)bm * Kdim + kt * 64 + lch * 8;
        const __half* Bg = Bt + (size_t)bn * Kdim + kt * 64 + lch * 8;
        #pragma unroll
        for (int i = 0; i < 4; i++) {
            int r = lrow + i * 32;
            uint32_t sw = (uint32_t)(lch ^ (r & 7)) << 4;
            cp_async16(base + r * 128 + sw,         Ag + (size_t)r * Kdim);
            cp_async16(base + 16384 + r * 128 + sw, Bg + (size_t)r * Kdim);
        }
        cp_commit();
    };

    loadTile(0, 0); loadTile(1, 1);

    const int ar0 = wm + (lane & 15);
    const int brr = wn + (lane & 7) + ((lane >> 4) << 3);
    const int a_l16 = (lane >> 4);
    const int b_l8  = (lane >> 3) & 1;

    int st = 0;
    for (int kt = 0; kt < KT; ++kt) {
        cp_wait<1>();
        __syncthreads();
        if (kt + 2 < KT) {
            int nst = st + 2; if (nst >= 3) nst -= 3;
            loadTile(kt + 2, nst);
        } else {
            cp_commit();
        }

        uint32_t Ab = sb + st * STAGE;
        uint32_t Bb = Ab + 16384;
        #pragma unroll
        for (int ks = 0; ks < 4; ++ks) {
            uint32_t a[2][4];
            int ach = ks * 2 + a_l16;
            #pragma unroll
            for (int mi = 0; mi < 2; mi++) {
                int r = ar0 + mi * 16;
                uint32_t addr = Ab + r * 128 + (((uint32_t)(ach ^ (r & 7))) << 4);
                ldsm4(a[mi][0], a[mi][1], a[mi][2], a[mi][3], addr);
            }
            int bch = ks * 2 + b_l8;
            #pragma unroll
            for (int ni = 0; ni < 4; ni++) {
                int r = brr + ni * 16;
                uint32_t addr = Bb + r * 128 + (((uint32_t)(bch ^ (r & 7))) << 4);
                uint32_t b0, b1, b2, b3;
                ldsm4(b0, b1, b2, b3, addr);
                #pragma unroll
                for (int mi = 0; mi < 2; mi++) {
                    mma16816(acc[mi][ni * 2    ], a[mi][0], a[mi][1], a[mi][2], a[mi][3], b0, b1);
                    mma16816(acc[mi][ni * 2 + 1], a[mi][0], a[mi][1], a[mi][2], a[mi][3], b2, b3);
                }
            }
        }
        if (++st == 3) st = 0;
    }

    // ---- epilogue: Q + bias -> smem QS (fp16, swizzled 256B rows) ----
    __syncthreads();
    {
        const int r0l = wm + (lane >> 2);
        const int c0l = wn + (lane & 3) * 2;
        #pragma unroll
        for (int mi = 0; mi < 2; mi++) {
            #pragma unroll
            for (int nj = 0; nj < 8; nj++) {
                int cl = c0l + nj * 8;
                float2 bv = *(const float2*)&bias[bn + cl];
                #pragma unroll
                for (int hf = 0; hf < 2; hf++) {
                    int rl = r0l + mi * 16 + hf * 8;
                    __half2 hv = __floats2half2_rn(acc[mi][nj][hf * 2] + bv.x,
                                                   acc[mi][nj][hf * 2 + 1] + bv.y);
                    uint32_t off = rl * 256 + ((uint32_t)(cl >> 6) << 7)
                                 + (((uint32_t)(((cl >> 3) & 7) ^ (rl & 7))) << 4)
                                 + (cl & 7) * 2;
                    *(__half2*)(smem + QS + off) = hv;
                }
            }
        }
    }
    {
        int ch = tid & 15, r16 = tid >> 4;
        #pragma unroll
        for (int i = 0; i < 4; i++) {
            int row = r16 + i * 16;
            uint32_t off = row * 256 + ((ch >> 3) << 7) + (((uint32_t)((ch & 7) ^ (row & 7))) << 4);
            cp_async16(sb + KS + off, kv + (size_t)(b * MM + row) * KVS + hh * DH + ch * 8);
        }
        cp_commit();
    }
    for (int i = tid; i < MM * DH; i += 256) {
        int m = i >> 7, d = i & 127;
        __half v = kv[(size_t)(b * MM + m) * KVS + DD + hh * DH + d];
        uint32_t off = d * 128 + (((uint32_t)((m >> 3) ^ (d & 7))) << 4) + (m & 7) * 2;
        *(__half*)(smem + VT + off) = v;
    }
    cp_wait<0>();
    __syncthreads();

    const int w = warp;
    const int arow = w * 16 + (lane & 15);
    const int a_hi = lane >> 4;
    const int brow = (lane & 7) + ((lane >> 4) << 3);
    const int bq_l8 = (lane >> 3) & 1;

    float sacc[8][4];
    #pragma unroll
    for (int i = 0; i < 8; i++)
        #pragma unroll
        for (int j = 0; j < 4; j++) sacc[i][j] = 0.f;

    #pragma unroll
    for (int ks = 0; ks < 8; ++ks) {
        int ach = ks * 2 + a_hi;
        uint32_t aaddr = sb + QS + arow * 256 + ((ach >> 3) << 7)
                       + (((uint32_t)((ach & 7) ^ (arow & 7))) << 4);
        uint32_t a0, a1, a2, a3;
        ldsm4(a0, a1, a2, a3, aaddr);
        int bch = ks * 2 + bq_l8;
        #pragma unroll
        for (int ni = 0; ni < 4; ++ni) {
            int r = brow + ni * 16;
            uint32_t baddr = sb + KS + r * 256 + ((bch >> 3) << 7)
                           + (((uint32_t)((bch & 7) ^ (r & 7))) << 4);
            uint32_t b0, b1, b2, b3;
            ldsm4(b0, b1, b2, b3, baddr);
            mma16816(sacc[ni * 2    ], a0, a1, a2, a3, b0, b1);
            mma16816(sacc[ni * 2 + 1], a0, a1, a2, a3, b2, b3);
        }
    }

    const float scale = 0.08838834764831844f;
    float mxA = -1e30f, mxB = -1e30f;
    #pragma unroll
    for (int nj = 0; nj < 8; nj++) {
        sacc[nj][0] *= scale; sacc[nj][1] *= scale;
        sacc[nj][2] *= scale; sacc[nj][3] *= scale;
        mxA = fmaxf(mxA, fmaxf(sacc[nj][0], sacc[nj][1]));
        mxB = fmaxf(mxB, fmaxf(sacc[nj][2], sacc[nj][3]));
    }
    mxA = fmaxf(mxA, __shfl_xor_sync(0xffffffffu, mxA, 1));
    mxA = fmaxf(mxA, __shfl_xor_sync(0xffffffffu, mxA, 2));
    mxB = fmaxf(mxB, __shfl_xor_sync(0xffffffffu, mxB, 1));
    mxB = fmaxf(mxB, __shfl_xor_sync(0xffffffffu, mxB, 2));

    const int prA = w * 16 + (lane >> 2);
    const int prB = prA + 8;
    float smA = 0.f, smB = 0.f;
    #pragma unroll
    for (int nj = 0; nj < 8; nj++) {
        float e0 = expf(sacc[nj][0] - mxA), e1 = expf(sacc[nj][1] - mxA);
        float e2 = expf(sacc[nj][2] - mxB), e3 = expf(sacc[nj][3] - mxB);
        smA += e0 + e1; smB += e2 + e3;
        __half2 hA = __floats2half2_rn(e0, e1);
        __half2 hB = __floats2half2_rn(e2, e3);
        uint32_t offA = prA * 128 + (((uint32_t)(nj ^ (prA & 7))) << 4) + (lane & 3) * 4;
        uint32_t offB = prB * 128 + (((uint32_t)(nj ^ (prB & 7))) << 4) + (lane & 3) * 4;
        *(__half2*)(smem + PS + offA) = hA;
        *(__half2*)(smem + PS + offB) = hB;
    }
    smA += __shfl_xor_sync(0xffffffffu, smA, 1);
    smA += __shfl_xor_sync(0xffffffffu, smA, 2);
    smB += __shfl_xor_sync(0xffffffffu, smB, 1);
    smB += __shfl_xor_sync(0xffffffffu, smB, 2);
    __syncwarp();

    float oacc[16][4];
    #pragma unroll
    for (int i = 0; i < 16; i++)
        #pragma unroll
        for (int j = 0; j < 4; j++) oacc[i][j] = 0.f;

    #pragma unroll
    for (int ks = 0; ks < 4; ++ks) {
        int ach = ks * 2 + a_hi;
        uint32_t aaddr = sb + PS + arow * 128 + (((uint32_t)(ach ^ (arow & 7))) << 4);
        uint32_t a0, a1, a2, a3;
        ldsm4(a0, a1, a2, a3, aaddr);
        int bch = ks * 2 + bq_l8;
        #pragma unroll
        for (int ni = 0; ni < 8; ++ni) {
            int r = brow + ni * 16;
            uint32_t baddr = sb + VT + r * 128 + (((uint32_t)(bch ^ (r & 7))) << 4);
            uint32_t b0, b1, b2, b3;
            ldsm4(b0, b1, b2, b3, baddr);
            mma16816(oacc[ni * 2    ], a0, a1, a2, a3, b0, b1);
            mma16816(oacc[ni * 2 + 1], a0, a1, a2, a3, b2, b3);
        }
    }

    float invA = 1.f / smA, invB = 1.f / smB;
    const size_t rowAoff = (size_t)(b * TT + t0 + prA) * DD + hh * DH;
    const size_t rowBoff = (size_t)(b * TT + t0 + prB) * DD + hh * DH;
    const int cbase = (lane & 3) * 2;
    #pragma unroll
    for (int nj = 0; nj < 16; nj++) {
        int col = cbase + nj * 8;
        __half2 hA = __floats2half2_rn(oacc[nj][0] * invA, oacc[nj][1] * invA);
        __half2 hB = __floats2half2_rn(oacc[nj][2] * invB, oacc[nj][3] * invB);
        *(__half2*)&ctx[rowAoff + col] = hA;
        *(__half2*)&ctx[rowBoff + col] = hB;
    }
}

// ---------------- launch ----------------
template<typename T>
static T* sym_addr(const void* sym) {
    void* p = nullptr;
    cudaGetSymbolAddress(&p, sym);
    return (T*)p;
}

extern "C" void kernel_launch(void* const* d_in, const int* in_sizes, int n_in,
                              void* d_out, int out_size)
{
    const float* h    = (const float*)d_in[0];
    const float* z    = (const float*)d_in[1];
    const float* ln_g = (const float*)d_in[2];
    const float* ln_b = (const float*)d_in[3];
    const float* Wq   = (const float*)d_in[4];
    const float* bq   = (const float*)d_in[5];
    const float* Wk   = (const float*)d_in[6];
    const float* bk   = (const float*)d_in[7];
    const float* Wv   = (const float*)d_in[8];
    const float* bv   = (const float*)d_in[9];
    const float* W1   = (const float*)d_in[10];
    const float* b1   = (const float*)d_in[11];
    const float* W2   = (const float*)d_in[12];
    const float* b2   = (const float*)d_in[13];
    const float* alpha= (const float*)d_in[14];
    float* out = (float*)d_out;

    __half* hn   = sym_addr<__half>(g_hn);
    __half* zr   = sym_addr<__half>(g_z);
    __half* wqT  = sym_addr<__half>(g_WqT);
    __half* wkvT = sym_addr<__half>(g_WkvT);
    __half* w1T  = sym_addr<__half>(g_W1T);
    __half* w2T  = sym_addr<__half>(g_W2T);
    float*  bkv  = sym_addr<float>(g_bkv);
    __half* kvb  = sym_addr<__half>(g_KV);
    __half* cx   = sym_addr<__half>(g_ctx);
    __half* gb   = sym_addr<__half>(g_G);

    const int SMEM = 3 * 32768;   // 96KB, 2 CTA/SM
    cudaFuncSetAttribute(gemm_fp16<0>, cudaFuncAttributeMaxDynamicSharedMemorySize, SMEM);
    cudaFuncSetAttribute(gemm_fp16<1>, cudaFuncAttributeMaxDynamicSharedMemorySize, SMEM);
    cudaFuncSetAttribute(gemm_fp16<2>, cudaFuncAttributeMaxDynamicSharedMemorySize, SMEM);
    cudaFuncSetAttribute(qproj_attn,  cudaFuncAttributeMaxDynamicSharedMemorySize, SMEM);

    cudaStream_t s1 = g_ss.s1, s2 = g_ss.s2;

    // fork both side streams off main
    cudaEventRecord(g_ss.evF, 0);
    cudaStreamWaitEvent(s1, g_ss.evF, 0);
    cudaStreamWaitEvent(s2, g_ss.evF, 0);

    // main: LN (critical path head)
    ln_kernel<<<BT, 256>>>(h, ln_g, ln_b, hn);

    // s1: Wq transpose (short pole), then FFN weight transposes (long lead time)
    transpose_half<<<dim3(DD / 32, DD / 32), dim3(32, 8), 0, s1>>>(Wq, wqT, DD, DD);
    cudaEventRecord(g_ss.evQ, s1);
    transpose_half<<<dim3(DFF / 32, DD / 32), dim3(32, 8), 0, s1>>>(W1, w1T, DD, DFF);
    cudaEventRecord(g_ss.ev1, s1);
    transpose_half<<<dim3(DD / 32, DFF / 32), dim3(32, 8), 0, s1>>>(W2, w2T, DFF, DD);
    cudaEventRecord(g_ss.ev2, s1);

    // s2: KV chain (z convert, Wk/Wv transposes, bias concat, KV GEMM)
    to_half_kernel<<<(BM_ * DZ / 4 + 255) / 256, 256, 0, s2>>>(z, zr, BM_ * DZ / 4);
    transpose_half<<<dim3(DD / 32, DZ / 32), dim3(32, 8), 0, s2>>>(Wk, wkvT, DZ, DD);
    transpose_half<<<dim3(DD / 32, DZ / 32), dim3(32, 8), 0, s2>>>(Wv, wkvT + (size_t)DD * DZ, DZ, DD);
    bias_concat_kernel<<<(DD + 255) / 256, 256, 0, s2>>>(bk, bv, bkv);
    gemm_fp16<0><<<(BM_ / 128) * (KVS / 128), 256, SMEM, s2>>>(zr, wkvT, bkv, kvb, BM_, KVS, DZ, nullptr, nullptr);
    cudaEventRecord(g_ss.evKV, s2);

    // main: fused Q-proj + attention (waits on WqT and KV)
    cudaStreamWaitEvent(0, g_ss.evQ, 0);
    cudaStreamWaitEvent(0, g_ss.evKV, 0);
    qproj_attn<<<(BT / 128) * (DD / 128), 256, SMEM>>>(hn, wqT, bq, kvb, cx);

    // main: FFN1, FFN2
    cudaStreamWaitEvent(0, g_ss.ev1, 0);
    gemm_fp16<1><<<(BT / 128) * (DFF / 128), 256, SMEM>>>(cx, w1T, b1, gb, BT, DFF, DD, nullptr, nullptr);

    cudaStreamWaitEvent(0, g_ss.ev2, 0);   // join: all side work merged
    gemm_fp16<2><<<(BT / 128) * (DD / 128), 256, SMEM>>>(gb, w2T, b2, out, BT, DD, DFF, h, alpha);
}

// round 16
// speedup vs baseline: 1.0081x; 1.0081x over previous
#include <cuda_runtime.h>
#include <cuda_fp16.h>
#include <math.h>
#include <stdint.h>

// ---------------- problem constants ----------------
#define BB    4
#define TT    4096
#define DD    2048
#define MM    64
#define DZ    512
#define HH    16
#define DH    128
#define DFF   8192
#define BT    (BB*TT)     // 16384
#define BM_   (BB*MM)     // 256
#define KVS   (2*DD)      // fused KV row stride

// ---------------- device scratch ----------------
__device__ __half g_hn [BT * DD];
__device__ __half g_z  [BM_ * DZ];
__device__ __half g_WqT [DD * DD];        // [N,K] K-major
__device__ __half g_WkvT[KVS * DZ];
__device__ __half g_W1T [DFF * DD];
__device__ __half g_W2T [DD * DFF];
__device__ float  g_bkv [KVS];
__device__ __half g_KV [BM_ * KVS];       // K cols 0..D-1, V cols D..2D-1
__device__ __half g_ctx[BT * DD];
__device__ __half g_G  [BT * DFF];

// ---------------- side streams + events (created at load, outside capture) ----
struct SideStream {
    cudaStream_t s1, s2;
    cudaEvent_t  evF, evQ, evKV, ev1, ev2;
    SideStream() {
        cudaStreamCreateWithFlags(&s1, cudaStreamNonBlocking);
        cudaStreamCreateWithFlags(&s2, cudaStreamNonBlocking);
        cudaEventCreateWithFlags(&evF,  cudaEventDisableTiming);
        cudaEventCreateWithFlags(&evQ,  cudaEventDisableTiming);
        cudaEventCreateWithFlags(&evKV, cudaEventDisableTiming);
        cudaEventCreateWithFlags(&ev1,  cudaEventDisableTiming);
        cudaEventCreateWithFlags(&ev2,  cudaEventDisableTiming);
    }
};
static SideStream g_ss;

// ---------------- helpers ----------------
__device__ __forceinline__ float gelu_fast(float x) {
    float u = 0.7978845608028654f * fmaf(0.044715f * x, x * x, x);
    float t;
    asm("tanh.approx.f32 %0, %1;" : "=f"(t) : "f"(u));
    return 0.5f * x * (1.f + t);
}
__device__ __forceinline__ void cp_async16(uint32_t s, const void* g) {
    asm volatile("cp.async.cg.shared.global [%0], [%1], 16;" :: "r"(s), "l"(g));
}
__device__ __forceinline__ void cp_commit() {
    asm volatile("cp.async.commit_group;");
}
template<int N> __device__ __forceinline__ void cp_wait() {
    asm volatile("cp.async.wait_group %0;" :: "n"(N));
}
__device__ __forceinline__ void ldsm4(uint32_t& r0, uint32_t& r1, uint32_t& r2, uint32_t& r3,
                                      uint32_t addr) {
    asm volatile("ldmatrix.sync.aligned.m8n8.x4.shared.b16 {%0,%1,%2,%3}, [%4];"
        : "=r"(r0), "=r"(r1), "=r"(r2), "=r"(r3) : "r"(addr));
}
__device__ __forceinline__ void mma16816(float* c,
                                         uint32_t a0, uint32_t a1, uint32_t a2, uint32_t a3,
                                         uint32_t b0, uint32_t b1) {
    asm volatile(
        "mma.sync.aligned.m16n8k16.row.col.f32.f16.f16.f32 "
        "{%0,%1,%2,%3}, {%4,%5,%6,%7}, {%8,%9}, {%0,%1,%2,%3};"
        : "+f"(c[0]), "+f"(c[1]), "+f"(c[2]), "+f"(c[3])
        : "r"(a0), "r"(a1), "r"(a2), "r"(a3), "r"(b0), "r"(b1));
}

// ---------------- elementwise fp32 -> fp16 ----------------
__global__ void to_half_kernel(const float* __restrict__ in, __half* __restrict__ out, int n4) {
    int i = blockIdx.x * blockDim.x + threadIdx.x;
    if (i < n4) {
        float4 v = ((const float4*)in)[i];
        __half2 h0 = __floats2half2_rn(v.x, v.y);
        __half2 h1 = __floats2half2_rn(v.z, v.w);
        uint2 o; o.x = *(uint32_t*)&h0; o.y = *(uint32_t*)&h1;
        ((uint2*)out)[i] = o;
    }
}

// ---------------- bias concat ----------------
__global__ void bias_concat_kernel(const float* __restrict__ bk, const float* __restrict__ bv,
                                   float* __restrict__ bkv) {
    int i = blockIdx.x * blockDim.x + threadIdx.x;
    if (i < DD) { bkv[i] = bk[i]; bkv[DD + i] = bv[i]; }
}

// ---------------- weight transpose: W[K,N] fp32 -> Wt[N,K] fp16 ----------------
__global__ __launch_bounds__(256) void transpose_half(
    const float* __restrict__ W, __half* __restrict__ Wt, int K, int N)
{
    __shared__ float t[32][33];
    int n0 = blockIdx.x * 32, k0 = blockIdx.y * 32;
    int tx = threadIdx.x, ty = threadIdx.y;   // 32 x 8
    #pragma unroll
    for (int i = 0; i < 32; i += 8)
        t[ty + i][tx] = W[(size_t)(k0 + ty + i) * N + n0 + tx];
    __syncthreads();
    int tid = ty * 32 + tx;
    int kl = (tid & 15) * 2;
    #pragma unroll
    for (int i = 0; i < 2; i++) {
        int nl = (tid >> 4) + i * 16;
        __half2 hv = __floats2half2_rn(t[kl][nl], t[kl + 1][nl]);
        *(__half2*)&Wt[(size_t)(n0 + nl) * K + k0 + kl] = hv;
    }
}

// ---------------- LayerNorm: fp32 in, fp16 out ----------------
__global__ __launch_bounds__(256) void ln_kernel(
    const float* __restrict__ h, const float* __restrict__ g,
    const float* __restrict__ b, __half* __restrict__ out)
{
    int row = blockIdx.x;
    const float4* x4 = (const float4*)(h + (size_t)row * DD);
    int tx = threadIdx.x;
    float4 v0 = x4[tx], v1 = x4[tx + 256];
    float s  = v0.x + v0.y + v0.z + v0.w + v1.x + v1.y + v1.z + v1.w;
    float s2 = v0.x*v0.x + v0.y*v0.y + v0.z*v0.z + v0.w*v0.w
             + v1.x*v1.x + v1.y*v1.y + v1.z*v1.z + v1.w*v1.w;
    int lane = tx & 31, warp = tx >> 5;
    #pragma unroll
    for (int o = 16; o; o >>= 1) {
        s  += __shfl_xor_sync(0xffffffffu, s,  o);
        s2 += __shfl_xor_sync(0xffffffffu, s2, o);
    }
    __shared__ float sh[16];
    if (lane == 0) { sh[warp] = s; sh[warp + 8] = s2; }
    __syncthreads();
    float ts = 0.f, ts2 = 0.f;
    #pragma unroll
    for (int i = 0; i < 8; i++) { ts += sh[i]; ts2 += sh[i + 8]; }
    float mu  = ts * (1.f / DD);
    float var = ts2 * (1.f / DD) - mu * mu;
    float inv = rsqrtf(var + 1e-5f);

    const float4* g4 = (const float4*)g;
    const float4* b4 = (const float4*)b;
    uint2* o4 = (uint2*)(out + (size_t)row * DD);
    #pragma unroll
    for (int half_i = 0; half_i < 2; half_i++) {
        float4 v = half_i ? v1 : v0;
        int idx = tx + half_i * 256;
        float4 ga = g4[idx], bb = b4[idx];
        float y0 = (v.x - mu) * inv * ga.x + bb.x;
        float y1 = (v.y - mu) * inv * ga.y + bb.y;
        float y2 = (v.z - mu) * inv * ga.z + bb.z;
        float y3 = (v.w - mu) * inv * ga.w + bb.w;
        __half2 h0 = __floats2half2_rn(y0, y1);
        __half2 h1 = __floats2half2_rn(y2, y3);
        uint2 o; o.x = *(uint32_t*)&h0; o.y = *(uint32_t*)&h1;
        o4[idx] = o;
    }
}

// ---------------- fp16 GEMM (champion, for KV/FFN1/FFN2) ----------------
template<int EPI>
__global__ void __launch_bounds__(256, 2) gemm_fp16(
    const __half* __restrict__ A, const __half* __restrict__ Bt,
    const float* __restrict__ bias, void* __restrict__ Cv,
    int Mdim, int Ndim, int Kdim,
    const float* __restrict__ res, const float* __restrict__ alpha)
{
    constexpr int STAGE = 32768;
    extern __shared__ __align__(128) char smem[];
    uint32_t sb = (uint32_t)__cvta_generic_to_shared(smem);
    const int tid  = threadIdx.x;
    const int lane = tid & 31, warp = tid >> 5;
    const int wm = (warp & 3) * 32, wn = (warp >> 2) * 64;

    int gm = Mdim >> 7, gn = Ndim >> 7;
    int pid = blockIdx.x;
    const int GRP = 8;
    int width = GRP * gn;
    int grp = pid / width;
    int first = grp * GRP;
    int sz = min(gm - first, GRP);
    int mt = first + (pid % sz);
    int nt = (pid % width) / sz;
    const int bm = mt << 7, bn = nt << 7;

    float acc[2][8][4];
    #pragma unroll
    for (int i = 0; i < 2; i++)
        #pragma unroll
        for (int j = 0; j < 8; j++)
            #pragma unroll
            for (int k = 0; k < 4; k++) acc[i][j][k] = 0.f;

    const int KT = Kdim >> 6;

    const int lrow = tid >> 3, lch = tid & 7;
    auto loadTile = [&](int kt, int st) {
        uint32_t base = sb + st * STAGE;
        const __half* Ag = A  + (size_t)bm * Kdim + kt * 64 + lch * 8;
        const __half* Bg = Bt + (size_t)bn * Kdim + kt * 64 + lch * 8;
        #pragma unroll
        for (int i = 0; i < 4; i++) {
            int r = lrow + i * 32;
            uint32_t sw = (uint32_t)(lch ^ (r & 7)) << 4;
            cp_async16(base + r * 128 + sw,         Ag + (size_t)r * Kdim);
            cp_async16(base + 16384 + r * 128 + sw, Bg + (size_t)r * Kdim);
        }
        cp_commit();
    };

    loadTile(0, 0); loadTile(1, 1);

    const int ar0 = wm + (lane & 15);
    const int brr = wn + (lane & 7) + ((lane >> 4) << 3);
    const int a_l16 = (lane >> 4);
    const int b_l8  = (lane >> 3) & 1;

    int st = 0;
    for (int kt = 0; kt < KT; ++kt) {
        cp_wait<1>();
        __syncthreads();
        if (kt + 2 < KT) {
            int nst = st + 2; if (nst >= 3) nst -= 3;
            loadTile(kt + 2, nst);
        } else {
            cp_commit();
        }

        uint32_t Ab = sb + st * STAGE;
        uint32_t Bb = Ab + 16384;
        #pragma unroll
        for (int ks = 0; ks < 4; ++ks) {
            uint32_t a[2][4];
            int ach = ks * 2 + a_l16;
            #pragma unroll
            for (int mi = 0; mi < 2; mi++) {
                int r = ar0 + mi * 16;
                uint32_t addr = Ab + r * 128 + (((uint32_t)(ach ^ (r & 7))) << 4);
                ldsm4(a[mi][0], a[mi][1], a[mi][2], a[mi][3], addr);
            }
            int bch = ks * 2 + b_l8;
            #pragma unroll
            for (int ni = 0; ni < 4; ni++) {
                int r = brr + ni * 16;
                uint32_t addr = Bb + r * 128 + (((uint32_t)(bch ^ (r & 7))) << 4);
                uint32_t b0, b1, b2, b3;
                ldsm4(b0, b1, b2, b3, addr);
                #pragma unroll
                for (int mi = 0; mi < 2; mi++) {
                    mma16816(acc[mi][ni * 2    ], a[mi][0], a[mi][1], a[mi][2], a[mi][3], b0, b1);
                    mma16816(acc[mi][ni * 2 + 1], a[mi][0], a[mi][1], a[mi][2], a[mi][3], b2, b3);
                }
            }
        }
        if (++st == 3) st = 0;
    }

    float ta = 0.f;
    if (EPI == 2) ta = tanhf(*alpha);
    const int r0 = bm + wm + (lane >> 2);
    const int c0 = bn + wn + (lane & 3) * 2;
    #pragma unroll
    for (int mi = 0; mi < 2; mi++) {
        #pragma unroll
        for (int nj = 0; nj < 8; nj++) {
            int col = c0 + nj * 8;
            float2 bv = *(const float2*)&bias[col];
            #pragma unroll
            for (int hf = 0; hf < 2; hf++) {
                int row = r0 + mi * 16 + hf * 8;
                float v0 = acc[mi][nj][hf * 2    ] + bv.x;
                float v1 = acc[mi][nj][hf * 2 + 1] + bv.y;
                size_t off = (size_t)row * Ndim + col;
                if (EPI == 0) {
                    __half2 hv = __floats2half2_rn(v0, v1);
                    *(__half2*)((__half*)Cv + off) = hv;
                } else if (EPI == 1) {
                    __half2 hv = __floats2half2_rn(gelu_fast(v0), gelu_fast(v1));
                    *(__half2*)((__half*)Cv + off) = hv;
                } else {
                    float2 rr = *(const float2*)&res[off];
                    float2 o; o.x = rr.x + ta * v0; o.y = rr.y + ta * v1;
                    *(float2*)((float*)Cv + off) = o;
                }
            }
        }
    }
}

// ---------------- FUSED Q-projection + cross-attention (champion) ----------------
__global__ void __launch_bounds__(256, 2) qproj_attn(
    const __half* __restrict__ A, const __half* __restrict__ Bt,
    const float* __restrict__ bias, const __half* __restrict__ kv,
    __half* __restrict__ ctx)
{
    constexpr int Mdim = BT, Ndim = DD, Kdim = DD;
    constexpr int STAGE = 32768;
    extern __shared__ __align__(128) char smem[];
    uint32_t sb = (uint32_t)__cvta_generic_to_shared(smem);
    const uint32_t QS = 0, KS = 32768, VT = 49152, PS = 65536;
    const int tid  = threadIdx.x;
    const int lane = tid & 31, warp = tid >> 5;
    const int wm = (warp & 3) * 32, wn = (warp >> 2) * 64;

    int gm = Mdim >> 7, gn = Ndim >> 7;
    int pid = blockIdx.x;
    const int GRP = 8;
    int width = GRP * gn;
    int grp = pid / width;
    int first = grp * GRP;
    int sz = min(gm - first, GRP);
    int mt = first + (pid % sz);
    int nt = (pid % width) / sz;
    const int bm = mt << 7, bn = nt << 7;
    const int b  = bm >> 12;
    const int t0 = bm & (TT - 1);
    const int hh = nt;

    float acc[2][8][4];
    #pragma unroll
    for (int i = 0; i < 2; i++)
        #pragma unroll
        for (int j = 0; j < 8; j++)
            #pragma unroll
            for (int k = 0; k < 4; k++) acc[i][j][k] = 0.f;

    const int KT = Kdim >> 6;

    const int lrow = tid >> 3, lch = tid & 7;
    auto loadTile = [&](int kt, int st) {
        uint32_t base = sb + st * STAGE;
        const __half* Ag = A  + (size_t)bm * Kdim + kt * 64 + lch * 8;
        const __half* Bg = Bt + (size_t)bn * Kdim + kt * 64 + lch * 8;
        #pragma unroll
        for (int i = 0; i < 4; i++) {
            int r = lrow + i * 32;
            uint32_t sw = (uint32_t)(lch ^ (r & 7)) << 4;
            cp_async16(base + r * 128 + sw,         Ag + (size_t)r * Kdim);
            cp_async16(base + 16384 + r * 128 + sw, Bg + (size_t)r * Kdim);
        }
        cp_commit();
    };

    loadTile(0, 0); loadTile(1, 1);

    const int ar0 = wm + (lane & 15);
    const int brr = wn + (lane & 7) + ((lane >> 4) << 3);
    const int a_l16 = (lane >> 4);
    const int b_l8  = (lane >> 3) & 1;

    int st = 0;
    for (int kt = 0; kt < KT; ++kt) {
        cp_wait<1>();
        __syncthreads();
        if (kt + 2 < KT) {
            int nst = st + 2; if (nst >= 3) nst -= 3;
            loadTile(kt + 2, nst);
        } else {
            cp_commit();
        }

        uint32_t Ab = sb + st * STAGE;
        uint32_t Bb = Ab + 16384;
        #pragma unroll
        for (int ks = 0; ks < 4; ++ks) {
            uint32_t a[2][4];
            int ach = ks * 2 + a_l16;
            #pragma unroll
            for (int mi = 0; mi < 2; mi++) {
                int r = ar0 + mi * 16;
                uint32_t addr = Ab + r * 128 + (((uint32_t)(ach ^ (r & 7))) << 4);
                ldsm4(a[mi][0], a[mi][1], a[mi][2], a[mi][3], addr);
            }
            int bch = ks * 2 + b_l8;
            #pragma unroll
            for (int ni = 0; ni < 4; ni++) {
                int r = brr + ni * 16;
                uint32_t addr = Bb + r * 128 + (((uint32_t)(bch ^ (r & 7))) << 4);
                uint32_t b0, b1, b2, b3;
                ldsm4(b0, b1, b2, b3, addr);
                #pragma unroll
                for (int mi = 0; mi < 2; mi++) {
                    mma16816(acc[mi][ni * 2    ], a[mi][0], a[mi][1], a[mi][2], a[mi][3], b0, b1);
                    mma16816(acc[mi][ni * 2 + 1], a[mi][0], a[mi][1], a[mi][2], a[mi][3], b2, b3);
                }
            }
        }
        if (++st == 3) st = 0;
    }

    // ---- epilogue: Q + bias -> smem QS (fp16, swizzled 256B rows) ----
    __syncthreads();
    {
        const int r0l = wm + (lane >> 2);
        const int c0l = wn + (lane & 3) * 2;
        #pragma unroll
        for (int mi = 0; mi < 2; mi++) {
            #pragma unroll
            for (int nj = 0; nj < 8; nj++) {
                int cl = c0l + nj * 8;
                float2 bv = *(const float2*)&bias[bn + cl];
                #pragma unroll
                for (int hf = 0; hf < 2; hf++) {
                    int rl = r0l + mi * 16 + hf * 8;
                    __half2 hv = __floats2half2_rn(acc[mi][nj][hf * 2] + bv.x,
                                                   acc[mi][nj][hf * 2 + 1] + bv.y);
                    uint32_t off = rl * 256 + ((uint32_t)(cl >> 6) << 7)
                                 + (((uint32_t)(((cl >> 3) & 7) ^ (rl & 7))) << 4)
                                 + (cl & 7) * 2;
                    *(__half2*)(smem + QS + off) = hv;
                }
            }
        }
    }
    {
        int ch = tid & 15, r16 = tid >> 4;
        #pragma unroll
        for (int i = 0; i < 4; i++) {
            int row = r16 + i * 16;
            uint32_t off = row * 256 + ((ch >> 3) << 7) + (((uint32_t)((ch & 7) ^ (row & 7))) << 4);
            cp_async16(sb + KS + off, kv + (size_t)(b * MM + row) * KVS + hh * DH + ch * 8);
        }
        cp_commit();
    }
    for (int i = tid; i < MM * DH; i += 256) {
        int m = i >> 7, d = i & 127;
        __half v = kv[(size_t)(b * MM + m) * KVS + DD + hh * DH + d];
        uint32_t off = d * 128 + (((uint32_t)((m >> 3) ^ (d & 7))) << 4) + (m & 7) * 2;
        *(__half*)(smem + VT + off) = v;
    }
    cp_wait<0>();
    __syncthreads();

    const int w = warp;
    const int arow = w * 16 + (lane & 15);
    const int a_hi = lane >> 4;
    const int brow = (lane & 7) + ((lane >> 4) << 3);
    const int bq_l8 = (lane >> 3) & 1;

    float sacc[8][4];
    #pragma unroll
    for (int i = 0; i < 8; i++)
        #pragma unroll
        for (int j = 0; j < 4; j++) sacc[i][j] = 0.f;

    #pragma unroll
    for (int ks = 0; ks < 8; ++ks) {
        int ach = ks * 2 + a_hi;
        uint32_t aaddr = sb + QS + arow * 256 + ((ach >> 3) << 7)
                       + (((uint32_t)((ach & 7) ^ (arow & 7))) << 4);
        uint32_t a0, a1, a2, a3;
        ldsm4(a0, a1, a2, a3, aaddr);
        int bch = ks * 2 + bq_l8;
        #pragma unroll
        for (int ni = 0; ni < 4; ++ni) {
            int r = brow + ni * 16;
            uint32_t baddr = sb + KS + r * 256 + ((bch >> 3) << 7)
                           + (((uint32_t)((bch & 7) ^ (r & 7))) << 4);
            uint32_t b0, b1, b2, b3;
            ldsm4(b0, b1, b2, b3, baddr);
            mma16816(sacc[ni * 2    ], a0, a1, a2, a3, b0, b1);
            mma16816(sacc[ni * 2 + 1], a0, a1, a2, a3, b2, b3);
        }
    }

    const float scale = 0.08838834764831844f;
    float mxA = -1e30f, mxB = -1e30f;
    #pragma unroll
    for (int nj = 0; nj < 8; nj++) {
        sacc[nj][0] *= scale; sacc[nj][1] *= scale;
        sacc[nj][2] *= scale; sacc[nj][3] *= scale;
        mxA = fmaxf(mxA, fmaxf(sacc[nj][0], sacc[nj][1]));
        mxB = fmaxf(mxB, fmaxf(sacc[nj][2], sacc[nj][3]));
    }
    mxA = fmaxf(mxA, __shfl_xor_sync(0xffffffffu, mxA, 1));
    mxA = fmaxf(mxA, __shfl_xor_sync(0xffffffffu, mxA, 2));
    mxB = fmaxf(mxB, __shfl_xor_sync(0xffffffffu, mxB, 1));
    mxB = fmaxf(mxB, __shfl_xor_sync(0xffffffffu, mxB, 2));

    const int prA = w * 16 + (lane >> 2);
    const int prB = prA + 8;
    float smA = 0.f, smB = 0.f;
    #pragma unroll
    for (int nj = 0; nj < 8; nj++) {
        float e0 = expf(sacc[nj][0] - mxA), e1 = expf(sacc[nj][1] - mxA);
        float e2 = expf(sacc[nj][2] - mxB), e3 = expf(sacc[nj][3] - mxB);
        smA += e0 + e1; smB += e2 + e3;
        __half2 hA = __floats2half2_rn(e0, e1);
        __half2 hB = __floats2half2_rn(e2, e3);
        uint32_t offA = prA * 128 + (((uint32_t)(nj ^ (prA & 7))) << 4) + (lane & 3) * 4;
        uint32_t offB = prB * 128 + (((uint32_t)(nj ^ (prB & 7))) << 4) + (lane & 3) * 4;
        *(__half2*)(smem + PS + offA) = hA;
        *(__half2*)(smem + PS + offB) = hB;
    }
    smA += __shfl_xor_sync(0xffffffffu, smA, 1);
    smA += __shfl_xor_sync(0xffffffffu, smA, 2);
    smB += __shfl_xor_sync(0xffffffffu, smB, 1);
    smB += __shfl_xor_sync(0xffffffffu, smB, 2);
    __syncwarp();

    float oacc[16][4];
    #pragma unroll
    for (int i = 0; i < 16; i++)
        #pragma unroll
        for (int j = 0; j < 4; j++) oacc[i][j] = 0.f;

    #pragma unroll
    for (int ks = 0; ks < 4; ++ks) {
        int ach = ks * 2 + a_hi;
        uint32_t aaddr = sb + PS + arow * 128 + (((uint32_t)(ach ^ (arow & 7))) << 4);
        uint32_t a0, a1, a2, a3;
        ldsm4(a0, a1, a2, a3, aaddr);
        int bch = ks * 2 + bq_l8;
        #pragma unroll
        for (int ni = 0; ni < 8; ++ni) {
            int r = brow + ni * 16;
            uint32_t baddr = sb + VT + r * 128 + (((uint32_t)(bch ^ (r & 7))) << 4);
            uint32_t b0, b1, b2, b3;
            ldsm4(b0, b1, b2, b3, baddr);
            mma16816(oacc[ni * 2    ], a0, a1, a2, a3, b0, b1);
            mma16816(oacc[ni * 2 + 1], a0, a1, a2, a3, b2, b3);
        }
    }

    float invA = 1.f / smA, invB = 1.f / smB;
    const size_t rowAoff = (size_t)(b * TT + t0 + prA) * DD + hh * DH;
    const size_t rowBoff = (size_t)(b * TT + t0 + prB) * DD + hh * DH;
    const int cbase = (lane & 3) * 2;
    #pragma unroll
    for (int nj = 0; nj < 16; nj++) {
        int col = cbase + nj * 8;
        __half2 hA = __floats2half2_rn(oacc[nj][0] * invA, oacc[nj][1] * invA);
        __half2 hB = __floats2half2_rn(oacc[nj][2] * invB, oacc[nj][3] * invB);
        *(__half2*)&ctx[rowAoff + col] = hA;
        *(__half2*)&ctx[rowBoff + col] = hB;
    }
}

// ---------------- launch ----------------
template<typename T>
static T* sym_addr(const void* sym) {
    void* p = nullptr;
    cudaGetSymbolAddress(&p, sym);
    return (T*)p;
}

extern "C" void kernel_launch(void* const* d_in, const int* in_sizes, int n_in,
                              void* d_out, int out_size)
{
    const float* h    = (const float*)d_in[0];
    const float* z    = (const float*)d_in[1];
    const float* ln_g = (const float*)d_in[2];
    const float* ln_b = (const float*)d_in[3];
    const float* Wq   = (const float*)d_in[4];
    const float* bq   = (const float*)d_in[5];
    const float* Wk   = (const float*)d_in[6];
    const float* bk   = (const float*)d_in[7];
    const float* Wv   = (const float*)d_in[8];
    const float* bv   = (const float*)d_in[9];
    const float* W1   = (const float*)d_in[10];
    const float* b1   = (const float*)d_in[11];
    const float* W2   = (const float*)d_in[12];
    const float* b2   = (const float*)d_in[13];
    const float* alpha= (const float*)d_in[14];
    float* out = (float*)d_out;

    __half* hn   = sym_addr<__half>(g_hn);
    __half* zr   = sym_addr<__half>(g_z);
    __half* wqT  = sym_addr<__half>(g_WqT);
    __half* wkvT = sym_addr<__half>(g_WkvT);
    __half* w1T  = sym_addr<__half>(g_W1T);
    __half* w2T  = sym_addr<__half>(g_W2T);
    float*  bkv  = sym_addr<float>(g_bkv);
    __half* kvb  = sym_addr<__half>(g_KV);
    __half* cx   = sym_addr<__half>(g_ctx);
    __half* gb   = sym_addr<__half>(g_G);

    const int SMEM = 3 * 32768;   // 96KB, 2 CTA/SM
    cudaFuncSetAttribute(gemm_fp16<0>, cudaFuncAttributeMaxDynamicSharedMemorySize, SMEM);
    cudaFuncSetAttribute(gemm_fp16<1>, cudaFuncAttributeMaxDynamicSharedMemorySize, SMEM);
    cudaFuncSetAttribute(gemm_fp16<2>, cudaFuncAttributeMaxDynamicSharedMemorySize, SMEM);
    cudaFuncSetAttribute(qproj_attn,  cudaFuncAttributeMaxDynamicSharedMemorySize, SMEM);

    cudaStream_t s1 = g_ss.s1, s2 = g_ss.s2;

    // fork both side streams off main
    cudaEventRecord(g_ss.evF, 0);
    cudaStreamWaitEvent(s1, g_ss.evF, 0);
    cudaStreamWaitEvent(s2, g_ss.evF, 0);

    // main: LN (critical path head)
    ln_kernel<<<BT, 256>>>(h, ln_g, ln_b, hn);

    // s2: KV chain (z convert, Wk/Wv transposes, bias concat, KV GEMM)
    to_half_kernel<<<(BM_ * DZ / 4 + 255) / 256, 256, 0, s2>>>(z, zr, BM_ * DZ / 4);
    transpose_half<<<dim3(DD / 32, DZ / 32), dim3(32, 8), 0, s2>>>(Wk, wkvT, DZ, DD);
    transpose_half<<<dim3(DD / 32, DZ / 32), dim3(32, 8), 0, s2>>>(Wv, wkvT + (size_t)DD * DZ, DZ, DD);
    bias_concat_kernel<<<(DD + 255) / 256, 256, 0, s2>>>(bk, bv, bkv);
    gemm_fp16<0><<<(BM_ / 128) * (KVS / 128), 256, SMEM, s2>>>(zr, wkvT, bkv, kvb, BM_, KVS, DZ, nullptr, nullptr);
    cudaEventRecord(g_ss.evKV, s2);

    // s1: Wq transpose (short pole); FFN transposes gated behind evKV so they
    // run inside the qproj_attn window (tensor-bound, HBM idle), NOT during
    // the bandwidth-critical pre-qproj window.
    transpose_half<<<dim3(DD / 32, DD / 32), dim3(32, 8), 0, s1>>>(Wq, wqT, DD, DD);
    cudaEventRecord(g_ss.evQ, s1);
    cudaStreamWaitEvent(s1, g_ss.evKV, 0);
    transpose_half<<<dim3(DFF / 32, DD / 32), dim3(32, 8), 0, s1>>>(W1, w1T, DD, DFF);
    cudaEventRecord(g_ss.ev1, s1);
    transpose_half<<<dim3(DD / 32, DFF / 32), dim3(32, 8), 0, s1>>>(W2, w2T, DFF, DD);
    cudaEventRecord(g_ss.ev2, s1);

    // main: fused Q-proj + attention (waits on WqT and KV)
    cudaStreamWaitEvent(0, g_ss.evQ, 0);
    cudaStreamWaitEvent(0, g_ss.evKV, 0);
    qproj_attn<<<(BT / 128) * (DD / 128), 256, SMEM>>>(hn, wqT, bq, kvb, cx);

    // main: FFN1, FFN2
    cudaStreamWaitEvent(0, g_ss.ev1, 0);
    gemm_fp16<1><<<(BT / 128) * (DFF / 128), 256, SMEM>>>(cx, w1T, b1, gb, BT, DFF, DD, nullptr, nullptr);

    cudaStreamWaitEvent(0, g_ss.ev2, 0);   // join: all side work merged
    gemm_fp16<2><<<(BT / 128) * (DD / 128), 256, SMEM>>>(gb, w2T, b2, out, BT, DD, DFF, h, alpha);
}